// round 16
// baseline (speedup 1.0000x reference)
#include <cuda_runtime.h>
#include <cuda_bf16.h>
#include <cstdint>

#define BATCH 256
#define NN 256
#define MM 256
#define DIM 32
#define LOG2E 1.4426950408889634f
#define LN2F 0.69314718055994531f
#define SBIG (1e8f * LOG2E)

__device__ float g_partial[BATCH];

__device__ __forceinline__ uint32_t smem_u32(const void* p) {
    uint32_t a;
    asm("{ .reg .u64 t; cvta.to.shared.u64 t, %1; cvt.u32.u64 %0, t; }" : "=r"(a) : "l"(p));
    return a;
}
__device__ __forceinline__ float ex2(float v) {
    float r;
    asm("ex2.approx.f32 %0, %1;" : "=f"(r) : "f"(v));
    return r;
}
__device__ __forceinline__ float lg2(float v) {
    float r;
    asm("lg2.approx.f32 %0, %1;" : "=f"(r) : "f"(v));
    return r;
}
__device__ __forceinline__ void ldmx4(uint32_t* r, uint32_t addr) {
    asm volatile("ldmatrix.sync.aligned.m8n8.x4.shared.b16 {%0,%1,%2,%3}, [%4];"
                 : "=r"(r[0]), "=r"(r[1]), "=r"(r[2]), "=r"(r[3]) : "r"(addr));
}
__device__ __forceinline__ void mma16816(float* c, const uint32_t* a, uint32_t b0,
                                         uint32_t b1) {
    asm volatile(
        "mma.sync.aligned.m16n8k16.row.col.f32.bf16.bf16.f32 "
        "{%0,%1,%2,%3}, {%4,%5,%6,%7}, {%8,%9}, {%0,%1,%2,%3};"
        : "+f"(c[0]), "+f"(c[1]), "+f"(c[2]), "+f"(c[3])
        : "r"(a[0]), "r"(a[1]), "r"(a[2]), "r"(a[3]), "r"(b0), "r"(b1));
}

#define NT 288
#define PITCHB 80
// smem byte offsets
#define XS0 0
#define XS1 20480
#define YS0 40960
#define YS1 61440
#define X2S0 81920
#define X2S1 82944
#define Y2S0 83968
#define Y2S1 84992
#define BAND0 86016                 // 4 slots x 4096 floats = 65536 B
#define BAND1 (86016 + 65536)       // 151552
#define BNDRY (151552 + 65536)      // 217088, 4 x 264 floats = 4224 B
#define SMEM_TOTAL (217088 + 4224)  // 221312 B

// stage one fp32 row (32 elems) -> bf16 smem row (pitch 80) + fp32 norm
__device__ __forceinline__ void stage_row(const float* src, char* dstbase,
                                          float* norm, int row) {
    float s = 0.f;
#pragma unroll
    for (int q = 0; q < 8; q++) {
        float4 v = *(const float4*)(src + q * 4);
        s = fmaf(v.x, v.x, fmaf(v.y, v.y, fmaf(v.z, v.z, fmaf(v.w, v.w, s))));
        uint2 wv;
        asm("cvt.rn.bf16x2.f32 %0, %1, %2;" : "=r"(wv.x) : "f"(v.y), "f"(v.x));
        asm("cvt.rn.bf16x2.f32 %0, %1, %2;" : "=r"(wv.y) : "f"(v.w), "f"(v.z));
        *(uint2*)(dstbase + row * PITCHB + q * 8) = wv;
    }
    norm[row] = s;
}

// produce 16x16 dist tile (rt, T1-rt) of band T1 into slot (T1&3) of band buf
__device__ __forceinline__ void produce_tile(uint32_t xsb, uint32_t ysb,
                                             const float* x2s, const float* y2s,
                                             float* band, int T1, int rt, int lane) {
    const int ct = T1 - rt;
    uint32_t afr[2][4];
    {
        uint32_t abase = xsb + (rt * 16 + (lane & 15)) * PITCHB + ((lane >> 4) << 4);
        ldmx4(afr[0], abase);
        ldmx4(afr[1], abase + 32);
    }
    uint32_t b0[4], b1[4];
    {
        uint32_t bbase = ysb + (ct * 16 + (lane & 7) + ((lane & 16) >> 1)) * PITCHB +
                         ((lane >> 3) & 1) * 16;
        ldmx4(b0, bbase);
        ldmx4(b1, bbase + 32);
    }
    float C0[4] = {0.f, 0.f, 0.f, 0.f};
    float C1[4] = {0.f, 0.f, 0.f, 0.f};
    mma16816(C0, afr[0], b0[0], b0[1]);
    mma16816(C0, afr[1], b1[0], b1[1]);
    mma16816(C1, afr[0], b0[2], b0[3]);
    mma16816(C1, afr[1], b1[2], b1[3]);

    const int rsub = lane >> 2, cpair = 2 * (lane & 3);
    const int r_lo = rt * 16 + rsub;
    const float x2lo = x2s[r_lo], x2hi = x2s[r_lo + 8];
    float* dst = band + (T1 & 3) * 4096 + rt * 256;
#pragma unroll
    for (int nt = 0; nt < 2; nt++) {
        const float* C = nt ? C1 : C0;
        const int cc = ct * 16 + nt * 8 + cpair;
        float2 yy = *(const float2*)(y2s + cc);
        float2 olo, ohi;
        olo.x = fmaxf(fmaf(-2.f, C[0], x2lo + yy.x), 0.f);
        olo.y = fmaxf(fmaf(-2.f, C[1], x2lo + yy.y), 0.f);
        ohi.x = fmaxf(fmaf(-2.f, C[2], x2hi + yy.x), 0.f);
        ohi.y = fmaxf(fmaf(-2.f, C[3], x2hi + yy.y), 0.f);
        const int cin = nt * 8 + cpair;
        *(float2*)(dst + rsub * 16 + cin) = olo;
        *(float2*)(dst + (rsub + 8) * 16 + cin) = ohi;
    }
}

// ---------------------------------------------------------------------------
// Fused kernel: dist tiles produced on the fly into a 4-SLOT smem band ring
// (slot = band index (rt+ct) & 3 — bands live 8 groups; production runs
// 2 bands ahead, race-free with one group of slack). Wavefront DP is the
// R12-proven structure: ILP-2, 128 CTAs x 288 threads, 4 diagonals/barrier,
// shfl neighbors, log2-domain cells.
// ---------------------------------------------------------------------------
__global__ __launch_bounds__(NT) void dtw_kernel(const float* __restrict__ x,
                                                 const float* __restrict__ y) {
    extern __shared__ char smem[];
    float* band0 = (float*)(smem + BAND0);
    float* band1 = (float*)(smem + BAND1);
    float* bnd = (float*)(smem + BNDRY);
    float* x2s0 = (float*)(smem + X2S0);
    float* x2s1 = (float*)(smem + X2S1);
    float* y2s0 = (float*)(smem + Y2S0);
    float* y2s1 = (float*)(smem + Y2S1);

    const int bb = blockIdx.x, t = threadIdx.x;
    const int w = t >> 5, l = t & 31;
    const int j = 29 * w + l - 2;          // owned column
    const int c = j - 1;                   // dist column index
    const bool cval = ((unsigned)c < 256u);
    const int ct = cval ? (c >> 4) : 0, cin = cval ? (c & 15) : 0;

    // stage x/y (bf16) + norms for both batches
    for (int row = t; row < 256; row += NT) {
        stage_row(x + ((size_t)(2 * bb) * 256 + row) * DIM, smem + XS0, x2s0, row);
        stage_row(x + ((size_t)(2 * bb + 1) * 256 + row) * DIM, smem + XS1, x2s1, row);
        stage_row(y + ((size_t)(2 * bb) * 256 + row) * DIM, smem + YS0, y2s0, row);
        stage_row(y + ((size_t)(2 * bb + 1) * 256 + row) * DIM, smem + YS1, y2s1, row);
    }
    __syncthreads();

    const uint32_t xsb0 = smem_u32(smem + XS0), ysb0 = smem_u32(smem + YS0);
    const uint32_t xsb1 = smem_u32(smem + XS1), ysb1 = smem_u32(smem + YS1);

    // prologue: bands 0 (tile 0) and 1 (tiles 0,1) for both batches
    if (w == 0) produce_tile(xsb0, ysb0, x2s0, y2s0, band0, 0, 0, l);
    else if (w == 1) produce_tile(xsb0, ysb0, x2s0, y2s0, band0, 1, 0, l);
    else if (w == 2) produce_tile(xsb0, ysb0, x2s0, y2s0, band0, 1, 1, l);
    else if (w == 4) produce_tile(xsb1, ysb1, x2s1, y2s1, band1, 0, 0, l);
    else if (w == 5) produce_tile(xsb1, ysb1, x2s1, y2s1, band1, 1, 0, l);
    else if (w == 6) produce_tile(xsb1, ysb1, x2s1, y2s1, band1, 1, 1, l);

    float v1_0 = SBIG, v0_0 = (j == 0) ? 0.f : SBIG;
    float v1_1 = SBIG, v0_1 = v0_0;

    // seed boundary for group 0
    if (w < 8 && l >= 29) {
        bnd[j] = v1_0; bnd[264 + j] = v0_0;
        bnd[528 + j] = v1_1; bnd[792 + j] = v0_1;
    }

    for (int g = 0; g < 128; ++g) {
        __syncthreads();   // produced bands visible + boundary exchange

        if (l < 3 && w > 0) {   // refresh redundant lanes
            v1_0 = bnd[j]; v0_0 = bnd[264 + j];
            v1_1 = bnd[528 + j]; v0_1 = bnd[792 + j];
        }

        const int p0 = 2 + 4 * g;
        // prefetch 4 dist values per batch; slot = tile band (rt+ct) & 3
        float dq0[4], dq1[4];
#pragma unroll
        for (int s = 0; s < 4; s++) {
            int r = p0 + s - j - 1;
            bool val = cval && ((unsigned)r < 256u);
            int rr = val ? r : 0;
            int off = ((((rr >> 4) + ct) & 3) << 12) + (((rr >> 4) & 15) << 8) +
                      ((rr & 15) << 4) + cin;
            dq0[s] = val ? band0[off] : 0.f;
            dq1[s] = val ? band1[off] : 0.f;
        }

        // produce band T+2 tiles (4 per batch per group; warps 0-3 b0, 4-7 b1)
        {
            const int T1 = (g >> 2) + 2;
            if (T1 <= 30 && w < 8) {
                int rt0 = T1 > 15 ? T1 - 15 : 0;
                int rt1 = T1 < 15 ? T1 : 15;
                int rt = rt0 + (g & 3) * 4 + (w & 3);
                if (rt <= rt1) {
                    if (w < 4)
                        produce_tile(xsb0, ysb0, x2s0, y2s0, band0, T1, rt, l);
                    else
                        produce_tile(xsb1, ysb1, x2s1, y2s1, band1, T1, rt, l);
                }
            }
        }

        float dgp0 = __shfl_up_sync(0xffffffffu, v0_0, 1);
        float dgp1 = __shfl_up_sync(0xffffffffu, v0_1, 1);

#pragma unroll
        for (int s = 0; s < 4; s++) {
            const int p = p0 + s;
            const int i = p - j;
            float lf0 = __shfl_up_sync(0xffffffffu, v1_0, 1);
            float lf1 = __shfl_up_sync(0xffffffffu, v1_1, 1);
            const bool val = cval && ((unsigned)(i - 1) < 256u);

            float up0 = v1_0, dg0 = dgp0;
            float up1 = v1_1, dg1 = dgp1;
            float a0 = fminf(up0, lf0), b0 = fmaxf(up0, lf0);
            float mn0 = fminf(a0, dg0);
            float mx0 = fmaxf(b0, dg0);
            float md0 = fmaxf(a0, fminf(b0, dg0));
            float a1 = fminf(up1, lf1), b1 = fmaxf(up1, lf1);
            float mn1 = fminf(a1, dg1);
            float mx1 = fmaxf(b1, dg1);
            float md1 = fmaxf(a1, fminf(b1, dg1));
            float s0 = 1.0f + ex2(mn0 - md0) + ex2(mn0 - mx0);
            float s1 = 1.0f + ex2(mn1 - md1) + ex2(mn1 - mx1);
            float nv0 = fmaf(dq0[s], LOG2E, mn0) - lg2(s0);
            float nv1 = fmaf(dq1[s], LOG2E, mn1) - lg2(s1);
            nv0 = val ? nv0 : SBIG;
            nv1 = val ? nv1 : SBIG;

            if (p == NN + MM && j == MM) {
                g_partial[2 * bb] = nv0 * LN2F;
                g_partial[2 * bb + 1] = nv1 * LN2F;
            }
            dgp0 = lf0; dgp1 = lf1;
            v0_0 = v1_0; v1_0 = nv0;
            v0_1 = v1_1; v1_1 = nv1;
        }

        if (w < 8 && l >= 29) {   // publish boundary for next warp's lanes 0-2
            bnd[j] = v1_0; bnd[264 + j] = v0_0;
            bnd[528 + j] = v1_1; bnd[792 + j] = v0_1;
        }
    }
}

// ---------------------------------------------------------------------------
// mean over batches -> scalar output
// ---------------------------------------------------------------------------
__global__ __launch_bounds__(256) void reduce_kernel(float* __restrict__ out) {
    __shared__ float sb[256];
    int t = threadIdx.x;
    sb[t] = g_partial[t];
    __syncthreads();
    for (int s = 128; s > 0; s >>= 1) {
        if (t < s) sb[t] += sb[t + s];
        __syncthreads();
    }
    if (t == 0) out[0] = sb[0] * (1.0f / BATCH);
}

extern "C" void kernel_launch(void* const* d_in, const int* in_sizes, int n_in,
                              void* d_out, int out_size) {
    (void)in_sizes; (void)n_in; (void)out_size;
    const float* x = (const float*)d_in[0];
    const float* y = (const float*)d_in[1];
    float* out = (float*)d_out;

    cudaFuncSetAttribute(dtw_kernel, cudaFuncAttributeMaxDynamicSharedMemorySize,
                         SMEM_TOTAL);

    dtw_kernel<<<BATCH / 2, NT, SMEM_TOTAL>>>(x, y);
    reduce_kernel<<<1, 256>>>(out);
}